// round 4
// baseline (speedup 1.0000x reference)
#include <cuda_runtime.h>

// Problem constants (fixed by reference: B=4, C=256, CQ=32, H=W=64)
#define B_   4
#define C_   256
#define CQ_  32
#define N_   4096

typedef unsigned long long u64;

// Scratch (allocation-free rule: __device__ globals)
__device__ float g_q[B_ * CQ_ * N_];   // [B][CQ][N]
__device__ float g_k[B_ * CQ_ * N_];   // [B][CQ][N]
__device__ float g_v[B_ * N_ * C_];    // [B][N][C]  (channel-contiguous)

// ---------------------------------------------------------------------------
// Packed fp32x2 helpers (sm_103a FFMA2; exact fp32 semantics, 2 FMAs/issue)
// ---------------------------------------------------------------------------
__device__ __forceinline__ void fma2(u64& d, u64 a, u64 b) {
    asm("fma.rn.f32x2 %0, %1, %2, %0;" : "+l"(d) : "l"(a), "l"(b));
}
__device__ __forceinline__ void mul2(u64& d, u64 a) {
    asm("mul.rn.f32x2 %0, %1, %0;" : "+l"(d) : "l"(a));
}
__device__ __forceinline__ u64 splat2(float x) {
    u64 d;
    asm("mov.b64 %0, {%1, %1};" : "=l"(d) : "r"(__float_as_uint(x)));
    return d;
}
__device__ __forceinline__ void unpack2(float& lo, float& hi, u64 v) {
    unsigned a, b;
    asm("mov.b64 {%0, %1}, %2;" : "=r"(a), "=r"(b) : "l"(v));
    lo = __uint_as_float(a);
    hi = __uint_as_float(b);
}

// ---------------------------------------------------------------------------
// cp.async helpers (16B global->shared, bypassing the register file)
// ---------------------------------------------------------------------------
__device__ __forceinline__ void cp16(void* smem, const void* g) {
    unsigned s = (unsigned)__cvta_generic_to_shared(smem);
    asm volatile("cp.async.ca.shared.global [%0], [%1], 16;" :: "r"(s), "l"(g));
}
__device__ __forceinline__ void cp_commit() {
    asm volatile("cp.async.commit_group;");
}
template <int N>
__device__ __forceinline__ void cp_wait() {
    asm volatile("cp.async.wait_group %0;" :: "n"(N));
}

// ---------------------------------------------------------------------------
// Projection: out = (W @ X + bias) * mask?
// Tile: 32 o x 128 n, K chunks of 32. 256 threads, each computes 4x4 outputs.
// TRANSPOSE_OUT: store as [n][o] (channel-contiguous) for the V tensor.
// ---------------------------------------------------------------------------
template <bool MASK, bool TRANSPOSE_OUT>
__global__ __launch_bounds__(256)
void proj_kernel(const float* __restrict__ X, const float* __restrict__ W,
                 const float* __restrict__ bias, const float* __restrict__ mask,
                 float* __restrict__ out, int O)
{
    const int b  = blockIdx.z;
    const int o0 = blockIdx.y * 32;
    const int n0 = blockIdx.x * 128;
    const int t  = threadIdx.x;
    const int tx = t & 31;   // n group (4 floats)
    const int ty = t >> 5;   // o group (4 rows)

    __shared__ float xs[32][128];   // [k][n]
    __shared__ float ws[32][33];    // [k][o], padded

    float acc[4][4];
#pragma unroll
    for (int i = 0; i < 4; i++)
#pragma unroll
        for (int j = 0; j < 4; j++) acc[i][j] = 0.f;

    const float* Xb = X + (size_t)b * C_ * N_ + n0;

    for (int kb = 0; kb < C_; kb += 32) {
#pragma unroll
        for (int r = 0; r < 4; r++) {
            int idx = t + r * 256;
            int kr  = idx >> 5;
            int c4  = idx & 31;
            *(float4*)&xs[kr][c4 * 4] =
                *(const float4*)(Xb + (size_t)(kb + kr) * N_ + c4 * 4);
        }
#pragma unroll
        for (int r = 0; r < 4; r++) {
            int idx = t + r * 256;
            int oo  = idx >> 5;
            int kk  = idx & 31;
            ws[kk][oo] = W[(size_t)(o0 + oo) * C_ + kb + kk];
        }
        __syncthreads();

#pragma unroll
        for (int k = 0; k < 32; k++) {
            float4 xv = *(float4*)&xs[k][tx * 4];
            float w0 = ws[k][ty * 4 + 0];
            float w1 = ws[k][ty * 4 + 1];
            float w2 = ws[k][ty * 4 + 2];
            float w3 = ws[k][ty * 4 + 3];
            acc[0][0] += w0 * xv.x; acc[0][1] += w0 * xv.y; acc[0][2] += w0 * xv.z; acc[0][3] += w0 * xv.w;
            acc[1][0] += w1 * xv.x; acc[1][1] += w1 * xv.y; acc[1][2] += w1 * xv.z; acc[1][3] += w1 * xv.w;
            acc[2][0] += w2 * xv.x; acc[2][1] += w2 * xv.y; acc[2][2] += w2 * xv.z; acc[2][3] += w2 * xv.w;
            acc[3][0] += w3 * xv.x; acc[3][1] += w3 * xv.y; acc[3][2] += w3 * xv.z; acc[3][3] += w3 * xv.w;
        }
        __syncthreads();
    }

    if (TRANSPOSE_OUT) {
        // out[b][n][o] — float4 over o (channel-contiguous)
        float bs0 = bias[o0 + ty * 4 + 0];
        float bs1 = bias[o0 + ty * 4 + 1];
        float bs2 = bias[o0 + ty * 4 + 2];
        float bs3 = bias[o0 + ty * 4 + 3];
#pragma unroll
        for (int nn = 0; nn < 4; nn++) {
            int n = n0 + tx * 4 + nn;
            float4 r;
            r.x = acc[0][nn] + bs0;
            r.y = acc[1][nn] + bs1;
            r.z = acc[2][nn] + bs2;
            r.w = acc[3][nn] + bs3;
            *(float4*)(out + ((size_t)b * N_ + n) * C_ + o0 + ty * 4) = r;
        }
    } else {
        float4 mv = make_float4(1.f, 1.f, 1.f, 1.f);
        if (MASK) mv = *(const float4*)(mask + (size_t)b * N_ + n0 + tx * 4);
#pragma unroll
        for (int oo = 0; oo < 4; oo++) {
            int o = o0 + ty * 4 + oo;
            float bs = bias[o];
            float4 r;
            r.x = (acc[oo][0] + bs) * mv.x;
            r.y = (acc[oo][1] + bs) * mv.y;
            r.z = (acc[oo][2] + bs) * mv.z;
            r.w = (acc[oo][3] + bs) * mv.w;
            *(float4*)(out + ((size_t)b * O + o) * N_ + n0 + tx * 4) = r;
        }
    }
}

// ---------------------------------------------------------------------------
// Flash-style attention: fp32x2-packed QK^T and P*V, parallel softmax,
// cp.async double-buffered K/V. Per CTA = (batch, 64-query tile).
// ---------------------------------------------------------------------------
// SMEM layout (floats):
//  qs  : [32][64]        off 0       (2048)
//  ks2 : [2][32][36]     off 2048    (2304)
//  ps  : [32][68]        off 4352    (2176)   scores/probs, [j][i]
//  vs2 : [2][32][260]    off 6528    (16640)  [j][c] channel-contiguous
//  m   : [64]            off 23168
//  l   : [64]            off 23232
//  cr  : [64]            off 23296
#define ATTN_SMEM_FLOATS 23360
#define ATTN_SMEM_BYTES  (ATTN_SMEM_FLOATS * 4)
#define NTILES (N_ / 32)

__global__ __launch_bounds__(256, 2)
void attn_kernel(const float* __restrict__ q, const float* __restrict__ k,
                 const float* __restrict__ v, const float* __restrict__ x,
                 const float* __restrict__ gamma, float* __restrict__ out)
{
    extern __shared__ float sm[];
    float* qs  = sm;                 // [32][64]
    float* ks0 = sm + 2048;          // [32][36]
    float* ks1 = sm + 2048 + 1152;
    float* ps  = sm + 4352;          // [32][68]
    float* vs0 = sm + 6528;          // [32][260]
    float* vs1 = sm + 6528 + 8320;
    float* msh = sm + 23168;
    float* lsh = sm + 23232;
    float* csh = sm + 23296;

    const int b   = blockIdx.y;
    const int qb0 = blockIdx.x * 64;
    const int t   = threadIdx.x;

    const float* qp = q + (size_t)b * CQ_ * N_;
    const float* kp = k + (size_t)b * CQ_ * N_;
    const float* vp = v + (size_t)b * N_ * C_;

    // per-thread copy coordinates (constant across tiles)
    const int kc  = t >> 3;          // k-tile channel row
    const int kj4 = (t & 7) * 4;     // k-tile j offset

    // issue tile 0
    {
        cp16(&ks0[kc * 36 + kj4], kp + (size_t)kc * N_ + kj4);
#pragma unroll
        for (int r = 0; r < 8; r++) {
            int idx = t + r * 256;
            int j   = idx >> 6;
            int c4  = (idx & 63) * 4;
            cp16(&vs0[j * 260 + c4], vp + (size_t)j * C_ + c4);
        }
        cp_commit();
    }

    // load q tile [32][64]
#pragma unroll
    for (int r = 0; r < 2; r++) {
        int idx = t + r * 256;
        int c   = idx >> 4;
        int i4  = idx & 15;
        *(float4*)&qs[c * 64 + i4 * 4] =
            *(const float4*)(qp + (size_t)c * N_ + qb0 + i4 * 4);
    }
    if (t < 64) { msh[t] = -INFINITY; lsh[t] = 0.f; }

    const int i0 = (t & 15) * 4;     // 4 queries per thread (PV stage)
    const int c0 = (t >> 4) * 16;    // 16 channels per thread (8 pairs)

    // softmax mapping: 4 lanes per query, warp-adjacent (shfl-able)
    const int sq = t >> 2;           // query 0..63
    const int sp = t & 3;            // key-slice 0..3 (8 keys each)

    u64 acc2[4][8];
#pragma unroll
    for (int qq = 0; qq < 4; qq++)
#pragma unroll
        for (int p = 0; p < 8; p++) acc2[qq][p] = 0ull;

    for (int it = 0; it < NTILES; it++) {
        float* ks = (it & 1) ? ks1 : ks0;
        float* vs = (it & 1) ? vs1 : vs0;

        // issue tile it+1 into the other buffer (its readers finished at the
        // trailing __syncthreads of iteration it-1)
        if (it + 1 < NTILES) {
            float* ksn = (it & 1) ? ks0 : ks1;
            float* vsn = (it & 1) ? vs0 : vs1;
            int j0n = (it + 1) * 32;
            cp16(&ksn[kc * 36 + kj4], kp + (size_t)kc * N_ + j0n + kj4);
#pragma unroll
            for (int r = 0; r < 8; r++) {
                int idx = t + r * 256;
                int j   = idx >> 6;
                int c4  = (idx & 63) * 4;
                cp16(&vsn[j * 260 + c4], vp + (size_t)(j0n + j) * C_ + c4);
            }
            cp_commit();
            cp_wait<1>();   // tile `it` complete
        } else {
            cp_wait<0>();
        }
        __syncthreads();

        // QK^T (f32x2 over query pairs): s[j][i], 8 scores/thread
        {
            int j  = t & 31;
            int ib = (t >> 5) * 8;
            u64 s2[4];
#pragma unroll
            for (int r = 0; r < 4; r++) s2[r] = 0ull;
#pragma unroll
            for (int c = 0; c < 32; c++) {
                u64 kv2 = splat2(ks[c * 36 + j]);
                u64 qv[4];
                const float4* qrow = (const float4*)&qs[c * 64 + ib];
                *(float4*)&qv[0] = qrow[0];
                *(float4*)&qv[2] = qrow[1];
                fma2(s2[0], kv2, qv[0]);
                fma2(s2[1], kv2, qv[1]);
                fma2(s2[2], kv2, qv[2]);
                fma2(s2[3], kv2, qv[3]);
            }
            float4* prow = (float4*)&ps[j * 68 + ib];
            prow[0] = *(float4*)&s2[0];
            prow[1] = *(float4*)&s2[2];
        }
        __syncthreads();

        // parallel online softmax: 4 lanes per query, 8 keys per lane
        {
            float mo = msh[sq];
            float mx = mo;
            float sc[8];
#pragma unroll
            for (int jj = 0; jj < 8; jj++) {
                sc[jj] = ps[(sp * 8 + jj) * 68 + sq];
                mx = fmaxf(mx, sc[jj]);
            }
            mx = fmaxf(mx, __shfl_xor_sync(0xffffffffu, mx, 1));
            mx = fmaxf(mx, __shfl_xor_sync(0xffffffffu, mx, 2));
            float sum = 0.f;
#pragma unroll
            for (int jj = 0; jj < 8; jj++) {
                float p = __expf(sc[jj] - mx);
                ps[(sp * 8 + jj) * 68 + sq] = p;
                sum += p;
            }
            sum += __shfl_xor_sync(0xffffffffu, sum, 1);
            sum += __shfl_xor_sync(0xffffffffu, sum, 2);
            if (sp == 0) {
                float corr = __expf(mo - mx);
                lsh[sq] = lsh[sq] * corr + sum;
                msh[sq] = mx;
                csh[sq] = corr;
            }
        }
        __syncthreads();

        // rescale accumulators (packed)
        {
            u64 cr0 = splat2(csh[i0 + 0]);
            u64 cr1 = splat2(csh[i0 + 1]);
            u64 cr2 = splat2(csh[i0 + 2]);
            u64 cr3 = splat2(csh[i0 + 3]);
#pragma unroll
            for (int p = 0; p < 8; p++) {
                mul2(acc2[0][p], cr0); mul2(acc2[1][p], cr1);
                mul2(acc2[2][p], cr2); mul2(acc2[3][p], cr3);
            }
        }

        // P*V, packed over channel pairs
#pragma unroll 4
        for (int j = 0; j < 32; j++) {
            float4 pq = *(float4*)&ps[j * 68 + i0];
            u64 p0 = splat2(pq.x);
            u64 p1 = splat2(pq.y);
            u64 p2 = splat2(pq.z);
            u64 p3 = splat2(pq.w);
            u64 vv[8];
            const float4* vrow = (const float4*)&vs[j * 260 + c0];
            *(float4*)&vv[0] = vrow[0];
            *(float4*)&vv[2] = vrow[1];
            *(float4*)&vv[4] = vrow[2];
            *(float4*)&vv[6] = vrow[3];
#pragma unroll
            for (int p = 0; p < 8; p++) {
                fma2(acc2[0][p], p0, vv[p]);
                fma2(acc2[1][p], p1, vv[p]);
                fma2(acc2[2][p], p2, vv[p]);
                fma2(acc2[3][p], p3, vv[p]);
            }
        }
        __syncthreads();
    }

    // unpack accumulators
    float acc[4][16];
#pragma unroll
    for (int qq = 0; qq < 4; qq++)
#pragma unroll
        for (int p = 0; p < 8; p++)
            unpack2(acc[qq][2 * p], acc[qq][2 * p + 1], acc2[qq][p]);

    // epilogue: out = gamma * acc / l + x
    float g  = gamma[0];
    float l0 = 1.f / lsh[i0 + 0];
    float l1 = 1.f / lsh[i0 + 1];
    float l2 = 1.f / lsh[i0 + 2];
    float l3 = 1.f / lsh[i0 + 3];
#pragma unroll
    for (int cc = 0; cc < 16; cc++) {
        int c = c0 + cc;
        const float* xr  = x   + ((size_t)b * C_ + c) * N_ + qb0 + i0;
        float*       orw = out + ((size_t)b * C_ + c) * N_ + qb0 + i0;
        float4 xv = *(const float4*)xr;
        float4 rr;
        rr.x = g * acc[0][cc] * l0 + xv.x;
        rr.y = g * acc[1][cc] * l1 + xv.y;
        rr.z = g * acc[2][cc] * l2 + xv.z;
        rr.w = g * acc[3][cc] * l3 + xv.w;
        *(float4*)orw = rr;
    }
}

// ---------------------------------------------------------------------------
// Launch
// ---------------------------------------------------------------------------
extern "C" void kernel_launch(void* const* d_in, const int* in_sizes, int n_in,
                              void* d_out, int out_size)
{
    const float* x     = (const float*)d_in[0];
    const float* mask  = (const float*)d_in[1];
    const float* Wq    = (const float*)d_in[2];
    const float* bq    = (const float*)d_in[3];
    const float* Wk    = (const float*)d_in[4];
    const float* bk    = (const float*)d_in[5];
    const float* Wv    = (const float*)d_in[6];
    const float* bv    = (const float*)d_in[7];
    const float* gamma = (const float*)d_in[8];
    float* out = (float*)d_out;

    float *gq, *gk, *gv;
    cudaGetSymbolAddress((void**)&gq, g_q);
    cudaGetSymbolAddress((void**)&gk, g_k);
    cudaGetSymbolAddress((void**)&gv, g_v);

    cudaFuncSetAttribute(attn_kernel,
                         cudaFuncAttributeMaxDynamicSharedMemorySize,
                         ATTN_SMEM_BYTES);

    proj_kernel<true , false><<<dim3(N_ / 128, CQ_ / 32, B_), 256>>>(x, Wq, bq, mask, gq, CQ_);
    proj_kernel<true , false><<<dim3(N_ / 128, CQ_ / 32, B_), 256>>>(x, Wk, bk, mask, gk, CQ_);
    proj_kernel<false, true ><<<dim3(N_ / 128, C_  / 32, B_), 256>>>(x, Wv, bv, nullptr, gv, C_);
    attn_kernel<<<dim3(N_ / 64, B_), 256, ATTN_SMEM_BYTES>>>(gq, gk, gv, x, gamma, out);
}

// round 6
// speedup vs baseline: 2.5261x; 2.5261x over previous
#include <cuda_runtime.h>
#include <cstdint>

// Problem constants (fixed by reference: B=4, C=256, CQ=32, H=W=64)
#define B_   4
#define C_   256
#define CQ_  32
#define N_   4096

// Scratch (allocation-free rule: __device__ globals)
__device__ float g_q[B_ * CQ_ * N_];   // [B][CQ][N]   (tf32-rounded)
__device__ float g_k[B_ * CQ_ * N_];   // [B][CQ][N]   (tf32-rounded)
__device__ float g_v[B_ * N_ * C_];    // [B][N][C]    (tf32-rounded, channel-contig)

// ---------------------------------------------------------------------------
// Helpers
// ---------------------------------------------------------------------------
__device__ __forceinline__ uint32_t fbits(float f) { return __float_as_uint(f); }

__device__ __forceinline__ float to_tf32(float x) {
    uint32_t r;
    asm("cvt.rna.tf32.f32 %0, %1;" : "=r"(r) : "f"(x));
    return __uint_as_float(r);
}

// mma.sync m16n8k8 tf32: D = A*B + D (fp32 accumulate)
__device__ __forceinline__ void mma8(float* d, const uint32_t* a,
                                     uint32_t b0, uint32_t b1) {
    asm("mma.sync.aligned.m16n8k8.row.col.f32.tf32.tf32.f32 "
        "{%0,%1,%2,%3},{%4,%5,%6,%7},{%8,%9},{%0,%1,%2,%3};"
        : "+f"(d[0]), "+f"(d[1]), "+f"(d[2]), "+f"(d[3])
        : "r"(a[0]), "r"(a[1]), "r"(a[2]), "r"(a[3]), "r"(b0), "r"(b1));
}

// cp.async helpers
__device__ __forceinline__ void cp16(void* smem, const void* g) {
    unsigned s = (unsigned)__cvta_generic_to_shared(smem);
    asm volatile("cp.async.ca.shared.global [%0], [%1], 16;" :: "r"(s), "l"(g));
}
__device__ __forceinline__ void cp_commit() {
    asm volatile("cp.async.commit_group;");
}
template <int N>
__device__ __forceinline__ void cp_wait() {
    asm volatile("cp.async.wait_group %0;" :: "n"(N));
}

// ---------------------------------------------------------------------------
// Projection: out = (W @ X + bias) * mask?, tf32-rounded stores.
// Tile: 32 o x 128 n, K chunks of 32. 256 threads, each computes 4x4 outputs.
// TRANSPOSE_OUT: store as [n][o] (channel-contiguous) for the V tensor.
// ---------------------------------------------------------------------------
template <bool MASK, bool TRANSPOSE_OUT>
__global__ __launch_bounds__(256)
void proj_kernel(const float* __restrict__ X, const float* __restrict__ W,
                 const float* __restrict__ bias, const float* __restrict__ mask,
                 float* __restrict__ out, int O)
{
    const int b  = blockIdx.z;
    const int o0 = blockIdx.y * 32;
    const int n0 = blockIdx.x * 128;
    const int t  = threadIdx.x;
    const int tx = t & 31;   // n group (4 floats)
    const int ty = t >> 5;   // o group (4 rows)

    __shared__ float xs[32][128];   // [k][n]
    __shared__ float ws[32][33];    // [k][o], padded

    float acc[4][4];
#pragma unroll
    for (int i = 0; i < 4; i++)
#pragma unroll
        for (int j = 0; j < 4; j++) acc[i][j] = 0.f;

    const float* Xb = X + (size_t)b * C_ * N_ + n0;

    for (int kb = 0; kb < C_; kb += 32) {
#pragma unroll
        for (int r = 0; r < 4; r++) {
            int idx = t + r * 256;
            int kr  = idx >> 5;
            int c4  = idx & 31;
            *(float4*)&xs[kr][c4 * 4] =
                *(const float4*)(Xb + (size_t)(kb + kr) * N_ + c4 * 4);
        }
#pragma unroll
        for (int r = 0; r < 4; r++) {
            int idx = t + r * 256;
            int oo  = idx >> 5;
            int kk  = idx & 31;
            ws[kk][oo] = W[(size_t)(o0 + oo) * C_ + kb + kk];
        }
        __syncthreads();

#pragma unroll
        for (int k = 0; k < 32; k++) {
            float4 xv = *(float4*)&xs[k][tx * 4];
            float w0 = ws[k][ty * 4 + 0];
            float w1 = ws[k][ty * 4 + 1];
            float w2 = ws[k][ty * 4 + 2];
            float w3 = ws[k][ty * 4 + 3];
            acc[0][0] += w0 * xv.x; acc[0][1] += w0 * xv.y; acc[0][2] += w0 * xv.z; acc[0][3] += w0 * xv.w;
            acc[1][0] += w1 * xv.x; acc[1][1] += w1 * xv.y; acc[1][2] += w1 * xv.z; acc[1][3] += w1 * xv.w;
            acc[2][0] += w2 * xv.x; acc[2][1] += w2 * xv.y; acc[2][2] += w2 * xv.z; acc[2][3] += w2 * xv.w;
            acc[3][0] += w3 * xv.x; acc[3][1] += w3 * xv.y; acc[3][2] += w3 * xv.z; acc[3][3] += w3 * xv.w;
        }
        __syncthreads();
    }

    if (TRANSPOSE_OUT) {
        // out[b][n][o] — float4 over o (channel-contiguous)
        float bs0 = bias[o0 + ty * 4 + 0];
        float bs1 = bias[o0 + ty * 4 + 1];
        float bs2 = bias[o0 + ty * 4 + 2];
        float bs3 = bias[o0 + ty * 4 + 3];
#pragma unroll
        for (int nn = 0; nn < 4; nn++) {
            int n = n0 + tx * 4 + nn;
            float4 r;
            r.x = to_tf32(acc[0][nn] + bs0);
            r.y = to_tf32(acc[1][nn] + bs1);
            r.z = to_tf32(acc[2][nn] + bs2);
            r.w = to_tf32(acc[3][nn] + bs3);
            *(float4*)(out + ((size_t)b * N_ + n) * C_ + o0 + ty * 4) = r;
        }
    } else {
        float4 mv = make_float4(1.f, 1.f, 1.f, 1.f);
        if (MASK) mv = *(const float4*)(mask + (size_t)b * N_ + n0 + tx * 4);
#pragma unroll
        for (int oo = 0; oo < 4; oo++) {
            int o = o0 + ty * 4 + oo;
            float bs = bias[o];
            float4 r;
            r.x = to_tf32((acc[oo][0] + bs) * mv.x);
            r.y = to_tf32((acc[oo][1] + bs) * mv.y);
            r.z = to_tf32((acc[oo][2] + bs) * mv.z);
            r.w = to_tf32((acc[oo][3] + bs) * mv.w);
            *(float4*)(out + ((size_t)b * O + o) * N_ + n0 + tx * 4) = r;
        }
    }
}

// ---------------------------------------------------------------------------
// Flash attention on tensor cores (mma.sync tf32), fp32 softmax.
// Per CTA = (batch, 64-query tile). Stream 32-key tiles, online softmax.
// GEMM1: warp w -> queries [(w>>1)*16, +16), keys [(w&1)*16, +16).
// GEMM2: warp w -> ALL 64 queries (4 m-tiles), channels [w*32, w*32+32).
// ---------------------------------------------------------------------------
// SMEM layout (floats); strides 40/264 are ≡8 (mod 32) -> bank 8*tig+gid
// is a perfect lane permutation (conflict-free B-fragment gathers).
//  qs  : [32][68]       off 0       (2176)   [channel][query]
//  ks2 : [2][32][40]    off 2176    (2560)   [channel][key]
//  ps  : [64][36]       off 4736    (2304)   [query][key] scores/probs
//  vs2 : [2][32][264]   off 7040    (16896)  [key][channel]
//  m/l/c: 3x[64]        off 23936
#define KS_S 40
#define VS_S 264
#define PS_S 36
#define ATTN_SMEM_FLOATS 24128
#define ATTN_SMEM_BYTES  (ATTN_SMEM_FLOATS * 4)
#define NTILES (N_ / 32)

__global__ __launch_bounds__(256, 2)
void attn_kernel(const float* __restrict__ q, const float* __restrict__ k,
                 const float* __restrict__ v, const float* __restrict__ x,
                 const float* __restrict__ gamma, float* __restrict__ out)
{
    extern __shared__ float sm[];
    float* qs  = sm;                   // [32][68]
    float* ks0 = sm + 2176;            // [32][40]
    float* ks1 = ks0 + 1280;
    float* ps  = sm + 4736;            // [64][36]
    float* vs0 = sm + 7040;            // [32][264]
    float* vs1 = vs0 + 8448;
    float* msh = sm + 23936;
    float* lsh = msh + 64;
    float* csh = msh + 128;

    const int b   = blockIdx.y;
    const int qb0 = blockIdx.x * 64;
    const int t   = threadIdx.x;

    const float* qp = q + (size_t)b * CQ_ * N_;
    const float* kp = k + (size_t)b * CQ_ * N_;
    const float* vp = v + (size_t)b * N_ * C_;

    // copy coordinates
    const int kc  = t >> 3;            // k-tile channel row
    const int kj4 = (t & 7) * 4;       // k-tile key offset

    // issue tile 0
    {
        cp16(&ks0[kc * KS_S + kj4], kp + (size_t)kc * N_ + kj4);
#pragma unroll
        for (int r = 0; r < 8; r++) {
            int idx = t + r * 256;
            int j   = idx >> 6;
            int c4  = (idx & 63) * 4;
            cp16(&vs0[j * VS_S + c4], vp + (size_t)j * C_ + c4);
        }
        cp_commit();
    }

    // load q tile into qs[c][i], stride 68
#pragma unroll
    for (int r = 0; r < 2; r++) {
        int idx = t + r * 256;
        int c   = idx >> 4;
        int i4  = idx & 15;
        *(float4*)&qs[c * 68 + i4 * 4] =
            *(const float4*)(qp + (size_t)c * N_ + qb0 + i4 * 4);
    }
    if (t < 64) { msh[t] = -INFINITY; lsh[t] = 0.f; }
    __syncthreads();

    // warp/fragment coordinates
    const int wid  = t >> 5;
    const int lane = t & 31;
    const int gid  = lane >> 2;        // 0..7
    const int tig  = lane & 3;         // 0..3
    const int m0   = (wid >> 1) * 16;  // GEMM1 query tile base
    const int n1   = (wid & 1) * 16;   // GEMM1 key base (2 n-tiles)
    const int ch0  = wid * 32;         // GEMM2 channel base (4 n-tiles)

    // preload Q A-fragments (tile-invariant): qa[kstep][4]
    uint32_t qa[4][4];
#pragma unroll
    for (int kk = 0; kk < 4; kk++) {
        qa[kk][0] = fbits(qs[(kk * 8 + tig)     * 68 + m0 + gid]);
        qa[kk][1] = fbits(qs[(kk * 8 + tig)     * 68 + m0 + gid + 8]);
        qa[kk][2] = fbits(qs[(kk * 8 + tig + 4) * 68 + m0 + gid]);
        qa[kk][3] = fbits(qs[(kk * 8 + tig + 4) * 68 + m0 + gid + 8]);
    }

    // softmax mapping: 4 lanes per query
    const int sq = t >> 2;
    const int sp = t & 3;

    // O accumulators: [m-tile][n-tile][4]
    float oa[4][4][4];
#pragma unroll
    for (int mt = 0; mt < 4; mt++)
#pragma unroll
        for (int nt = 0; nt < 4; nt++)
#pragma unroll
            for (int r = 0; r < 4; r++) oa[mt][nt][r] = 0.f;

    for (int it = 0; it < NTILES; it++) {
        float* ks = (it & 1) ? ks1 : ks0;
        float* vs = (it & 1) ? vs1 : vs0;

        if (it + 1 < NTILES) {
            float* ksn = (it & 1) ? ks0 : ks1;
            float* vsn = (it & 1) ? vs0 : vs1;
            int j0n = (it + 1) * 32;
            cp16(&ksn[kc * KS_S + kj4], kp + (size_t)kc * N_ + j0n + kj4);
#pragma unroll
            for (int r = 0; r < 8; r++) {
                int idx = t + r * 256;
                int j   = idx >> 6;
                int c4  = (idx & 63) * 4;
                cp16(&vsn[j * VS_S + c4], vp + (size_t)(j0n + j) * C_ + c4);
            }
            cp_commit();
            cp_wait<1>();
        } else {
            cp_wait<0>();
        }
        __syncthreads();   // tiles ready, ps free

        // ---- GEMM1: S[64 x 32] = Q x K^T (2 n-tiles per warp) ----
#pragma unroll
        for (int nt = 0; nt < 2; nt++) {
            float s[4] = {0.f, 0.f, 0.f, 0.f};
#pragma unroll
            for (int kk = 0; kk < 4; kk++) {
                uint32_t b0 = fbits(ks[(kk * 8 + tig)     * KS_S + n1 + nt * 8 + gid]);
                uint32_t b1 = fbits(ks[(kk * 8 + tig + 4) * KS_S + n1 + nt * 8 + gid]);
                mma8(s, qa[kk], b0, b1);
            }
            int j = n1 + nt * 8 + 2 * tig;
            *(float2*)&ps[(m0 + gid)     * PS_S + j] = make_float2(s[0], s[1]);
            *(float2*)&ps[(m0 + gid + 8) * PS_S + j] = make_float2(s[2], s[3]);
        }
        __syncthreads();

        // ---- online softmax (fp32 exact; 4 lanes per query) ----
        {
            float4 sa = *(float4*)&ps[sq * PS_S + sp * 8];
            float4 sb = *(float4*)&ps[sq * PS_S + sp * 8 + 4];
            float mo = msh[sq];
            float mx = mo;
            mx = fmaxf(mx, fmaxf(fmaxf(sa.x, sa.y), fmaxf(sa.z, sa.w)));
            mx = fmaxf(mx, fmaxf(fmaxf(sb.x, sb.y), fmaxf(sb.z, sb.w)));
            mx = fmaxf(mx, __shfl_xor_sync(0xffffffffu, mx, 1));
            mx = fmaxf(mx, __shfl_xor_sync(0xffffffffu, mx, 2));
            float4 pa, pb;
            pa.x = to_tf32(__expf(sa.x - mx));
            pa.y = to_tf32(__expf(sa.y - mx));
            pa.z = to_tf32(__expf(sa.z - mx));
            pa.w = to_tf32(__expf(sa.w - mx));
            pb.x = to_tf32(__expf(sb.x - mx));
            pb.y = to_tf32(__expf(sb.y - mx));
            pb.z = to_tf32(__expf(sb.z - mx));
            pb.w = to_tf32(__expf(sb.w - mx));
            float sum = pa.x + pa.y + pa.z + pa.w + pb.x + pb.y + pb.z + pb.w;
            sum += __shfl_xor_sync(0xffffffffu, sum, 1);
            sum += __shfl_xor_sync(0xffffffffu, sum, 2);
            *(float4*)&ps[sq * PS_S + sp * 8]     = pa;
            *(float4*)&ps[sq * PS_S + sp * 8 + 4] = pb;
            if (sp == 0) {
                float corr = __expf(mo - mx);
                lsh[sq] = lsh[sq] * corr + sum;
                msh[sq] = mx;
                csh[sq] = corr;
            }
        }
        __syncthreads();

        // ---- rescale O ----
#pragma unroll
        for (int mt = 0; mt < 4; mt++) {
            float cr0 = csh[mt * 16 + gid];
            float cr1 = csh[mt * 16 + gid + 8];
#pragma unroll
            for (int nt = 0; nt < 4; nt++) {
                oa[mt][nt][0] *= cr0; oa[mt][nt][1] *= cr0;
                oa[mt][nt][2] *= cr1; oa[mt][nt][3] *= cr1;
            }
        }

        // ---- GEMM2: O[64 x 32/warp] += P[64 x 32] x V[32 x 32-ch slice] ----
#pragma unroll
        for (int kt = 0; kt < 4; kt++) {
            // V B-fragments, hoisted: reused across all 4 m-tiles
            uint32_t vb[4][2];
            const float* vr0 = &vs[(kt * 8 + tig)     * VS_S + ch0 + gid];
            const float* vr1 = &vs[(kt * 8 + tig + 4) * VS_S + ch0 + gid];
#pragma unroll
            for (int nt = 0; nt < 4; nt++) {
                vb[nt][0] = fbits(vr0[nt * 8]);
                vb[nt][1] = fbits(vr1[nt * 8]);
            }
#pragma unroll
            for (int mt = 0; mt < 4; mt++) {
                uint32_t pA[4];
                pA[0] = fbits(ps[(mt * 16 + gid)     * PS_S + kt * 8 + tig]);
                pA[1] = fbits(ps[(mt * 16 + gid + 8) * PS_S + kt * 8 + tig]);
                pA[2] = fbits(ps[(mt * 16 + gid)     * PS_S + kt * 8 + tig + 4]);
                pA[3] = fbits(ps[(mt * 16 + gid + 8) * PS_S + kt * 8 + tig + 4]);
#pragma unroll
                for (int nt = 0; nt < 4; nt++)
                    mma8(oa[mt][nt], pA, vb[nt][0], vb[nt][1]);
            }
        }
        __syncthreads();   // protect ps/vs for next iteration
    }

    // ---- epilogue: out = gamma * O / l + x ----
    float g = gamma[0];
#pragma unroll
    for (int mt = 0; mt < 4; mt++) {
        float il0 = 1.f / lsh[mt * 16 + gid];
        float il1 = 1.f / lsh[mt * 16 + gid + 8];
        int row0 = qb0 + mt * 16 + gid;
        int row1 = row0 + 8;
#pragma unroll
        for (int nt = 0; nt < 4; nt++) {
            int c = ch0 + nt * 8 + 2 * tig;
            const float* x0 = x + ((size_t)b * C_ + c) * N_;
            float*       o0 = out + ((size_t)b * C_ + c) * N_;
            o0[row0]      = g * oa[mt][nt][0] * il0 + x0[row0];
            o0[N_ + row0] = g * oa[mt][nt][1] * il0 + x0[N_ + row0];
            o0[row1]      = g * oa[mt][nt][2] * il1 + x0[row1];
            o0[N_ + row1] = g * oa[mt][nt][3] * il1 + x0[N_ + row1];
        }
    }
}

// ---------------------------------------------------------------------------
// Launch
// ---------------------------------------------------------------------------
extern "C" void kernel_launch(void* const* d_in, const int* in_sizes, int n_in,
                              void* d_out, int out_size)
{
    const float* x     = (const float*)d_in[0];
    const float* mask  = (const float*)d_in[1];
    const float* Wq    = (const float*)d_in[2];
    const float* bq    = (const float*)d_in[3];
    const float* Wk    = (const float*)d_in[4];
    const float* bk    = (const float*)d_in[5];
    const float* Wv    = (const float*)d_in[6];
    const float* bv    = (const float*)d_in[7];
    const float* gamma = (const float*)d_in[8];
    float* out = (float*)d_out;

    float *gq, *gk, *gv;
    cudaGetSymbolAddress((void**)&gq, g_q);
    cudaGetSymbolAddress((void**)&gk, g_k);
    cudaGetSymbolAddress((void**)&gv, g_v);

    cudaFuncSetAttribute(attn_kernel,
                         cudaFuncAttributeMaxDynamicSharedMemorySize,
                         ATTN_SMEM_BYTES);

    proj_kernel<true , false><<<dim3(N_ / 128, CQ_ / 32, B_), 256>>>(x, Wq, bq, mask, gq, CQ_);
    proj_kernel<true , false><<<dim3(N_ / 128, CQ_ / 32, B_), 256>>>(x, Wk, bk, mask, gk, CQ_);
    proj_kernel<false, true ><<<dim3(N_ / 128, C_  / 32, B_), 256>>>(x, Wv, bv, nullptr, gv, C_);
    attn_kernel<<<dim3(N_ / 64, B_), 256, ATTN_SMEM_BYTES>>>(gq, gk, gv, x, gamma, out);
}

// round 9
// speedup vs baseline: 4.1081x; 1.6262x over previous
#include <cuda_runtime.h>
#include <cuda_bf16.h>
#include <cstdint>

// Problem constants (fixed by reference: B=4, C=256, CQ=32, H=W=64)
#define B_   4
#define C_   256
#define CQ_  32
#define N_   4096

typedef unsigned long long u64;

// Scratch (allocation-free rule: __device__ globals)
__device__ __nv_bfloat16 g_q[B_ * N_ * CQ_];   // [B][N][CQ]  (masked, channel-contig)
__device__ __nv_bfloat16 g_k[B_ * N_ * CQ_];   // [B][N][CQ]  (masked, channel-contig)
__device__ __nv_bfloat16 g_v[B_ * C_ * N_];    // [B][C][N]   (key-contig)

// ---------------------------------------------------------------------------
// Helpers
// ---------------------------------------------------------------------------
__device__ __forceinline__ uint32_t pack_bf16(float lo, float hi) {
    __nv_bfloat162 h = __floats2bfloat162_rn(lo, hi);   // .x = lo (low 16 bits)
    return *(uint32_t*)&h;
}

// mma m16n8k16 bf16: D = A*B + D (fp32 accumulate)
__device__ __forceinline__ void mma16(float* d, const uint32_t* a,
                                      uint32_t b0, uint32_t b1) {
    asm("mma.sync.aligned.m16n8k16.row.col.f32.bf16.bf16.f32 "
        "{%0,%1,%2,%3},{%4,%5,%6,%7},{%8,%9},{%0,%1,%2,%3};"
        : "+f"(d[0]), "+f"(d[1]), "+f"(d[2]), "+f"(d[3])
        : "r"(a[0]), "r"(a[1]), "r"(a[2]), "r"(a[3]), "r"(b0), "r"(b1));
}

// f32x2 packed math (projection kernels)
__device__ __forceinline__ void fma2(u64& d, u64 a, u64 b) {
    asm("fma.rn.f32x2 %0, %1, %2, %0;" : "+l"(d) : "l"(a), "l"(b));
}
__device__ __forceinline__ u64 splat2(float x) {
    u64 d;
    asm("mov.b64 %0, {%1, %1};" : "=l"(d) : "r"(__float_as_uint(x)));
    return d;
}
__device__ __forceinline__ void unpack2(float& lo, float& hi, u64 v) {
    unsigned a, b;
    asm("mov.b64 {%0, %1}, %2;" : "=r"(a), "=r"(b) : "l"(v));
    lo = __uint_as_float(a);
    hi = __uint_as_float(b);
}

// cp.async helpers (.cg = L2-only: K/V tiles are stream-once, keep L1 clean)
__device__ __forceinline__ void cp16(void* smem, const void* g) {
    unsigned s = (unsigned)__cvta_generic_to_shared(smem);
    asm volatile("cp.async.cg.shared.global [%0], [%1], 16;" :: "r"(s), "l"(g));
}
__device__ __forceinline__ void cp_commit() {
    asm volatile("cp.async.commit_group;");
}
template <int N>
__device__ __forceinline__ void cp_wait() {
    asm volatile("cp.async.wait_group %0;" :: "n"(N));
}

// ---------------------------------------------------------------------------
// Projection core: acc = W[32 o-rows] @ X-tile[k x 128n], f32x2-packed.
// Shared by the QK and V kernels below.
// ---------------------------------------------------------------------------
struct ProjAcc { u64 a[4][2]; };

__device__ __forceinline__ void proj_core(const float* __restrict__ X,
                                          const float* __restrict__ W,
                                          int b, int o0, int n0, int t,
                                          float xs[32][128], float ws[32][33],
                                          ProjAcc& pa)
{
#pragma unroll
    for (int i = 0; i < 4; i++) { pa.a[i][0] = 0ull; pa.a[i][1] = 0ull; }

    const int tx = t & 31;
    const int ty = t >> 5;
    const float* Xb = X + (size_t)b * C_ * N_ + n0;

    for (int kb = 0; kb < C_; kb += 32) {
#pragma unroll
        for (int r = 0; r < 4; r++) {
            int idx = t + r * 256;
            int kr  = idx >> 5;
            int c4  = idx & 31;
            *(float4*)&xs[kr][c4 * 4] =
                *(const float4*)(Xb + (size_t)(kb + kr) * N_ + c4 * 4);
        }
#pragma unroll
        for (int r = 0; r < 4; r++) {
            int idx = t + r * 256;
            int oo  = idx >> 5;
            int kk  = idx & 31;
            ws[kk][oo] = W[(size_t)(o0 + oo) * C_ + kb + kk];
        }
        __syncthreads();

#pragma unroll
        for (int k = 0; k < 32; k++) {
            const u64* xp = (const u64*)&xs[k][tx * 4];
            u64 x0 = xp[0], x1 = xp[1];
            u64 w0 = splat2(ws[k][ty * 4 + 0]);
            u64 w1 = splat2(ws[k][ty * 4 + 1]);
            u64 w2 = splat2(ws[k][ty * 4 + 2]);
            u64 w3 = splat2(ws[k][ty * 4 + 3]);
            fma2(pa.a[0][0], w0, x0); fma2(pa.a[0][1], w0, x1);
            fma2(pa.a[1][0], w1, x0); fma2(pa.a[1][1], w1, x1);
            fma2(pa.a[2][0], w2, x0); fma2(pa.a[2][1], w2, x1);
            fma2(pa.a[3][0], w3, x0); fma2(pa.a[3][1], w3, x1);
        }
        __syncthreads();
    }
}

// Q and K projections fused in one launch: blockIdx.y selects (W,b,out).
// Output [b][n][o] bf16 (channel-contig), mask applied.
__global__ __launch_bounds__(256)
void qk_proj_kernel(const float* __restrict__ X,
                    const float* __restrict__ Wq, const float* __restrict__ bq,
                    const float* __restrict__ Wk, const float* __restrict__ bk,
                    const float* __restrict__ mask,
                    __nv_bfloat16* __restrict__ outq,
                    __nv_bfloat16* __restrict__ outk)
{
    __shared__ float xs[32][128];
    __shared__ float ws[32][33];

    const int b  = blockIdx.z;
    const int n0 = blockIdx.x * 128;
    const int t  = threadIdx.x;
    const int tx = t & 31;
    const int ty = t >> 5;

    const bool isK = blockIdx.y != 0;
    const float* W    = isK ? Wk : Wq;
    const float* bias = isK ? bk : bq;
    __nv_bfloat16* out = isK ? outk : outq;

    ProjAcc pa;
    proj_core(X, W, b, 0, n0, t, xs, ws, pa);

    float acc[4][4];
#pragma unroll
    for (int oo = 0; oo < 4; oo++) {
        unpack2(acc[oo][0], acc[oo][1], pa.a[oo][0]);
        unpack2(acc[oo][2], acc[oo][3], pa.a[oo][1]);
    }

    float4 mv = *(const float4*)(mask + (size_t)b * N_ + n0 + tx * 4);
    float m[4] = {mv.x, mv.y, mv.z, mv.w};
    float bs0 = bias[ty * 4 + 0];
    float bs1 = bias[ty * 4 + 1];
    float bs2 = bias[ty * 4 + 2];
    float bs3 = bias[ty * 4 + 3];

#pragma unroll
    for (int nn = 0; nn < 4; nn++) {
        int n = n0 + tx * 4 + nn;
        uint2 pk;
        pk.x = pack_bf16((acc[0][nn] + bs0) * m[nn], (acc[1][nn] + bs1) * m[nn]);
        pk.y = pack_bf16((acc[2][nn] + bs2) * m[nn], (acc[3][nn] + bs3) * m[nn]);
        *(uint2*)(out + ((size_t)b * N_ + n) * CQ_ + ty * 4) = pk;
    }
}

// V projection: output [b][o][n] bf16 (key-contig), no mask.
__global__ __launch_bounds__(256)
void v_proj_kernel(const float* __restrict__ X, const float* __restrict__ W,
                   const float* __restrict__ bias,
                   __nv_bfloat16* __restrict__ out)
{
    __shared__ float xs[32][128];
    __shared__ float ws[32][33];

    const int b  = blockIdx.z;
    const int o0 = blockIdx.y * 32;
    const int n0 = blockIdx.x * 128;
    const int t  = threadIdx.x;
    const int tx = t & 31;
    const int ty = t >> 5;

    ProjAcc pa;
    proj_core(X, W, b, o0, n0, t, xs, ws, pa);

    float acc[4][4];
#pragma unroll
    for (int oo = 0; oo < 4; oo++) {
        unpack2(acc[oo][0], acc[oo][1], pa.a[oo][0]);
        unpack2(acc[oo][2], acc[oo][3], pa.a[oo][1]);
    }

    float bs[4] = {bias[o0 + ty * 4 + 0], bias[o0 + ty * 4 + 1],
                   bias[o0 + ty * 4 + 2], bias[o0 + ty * 4 + 3]};
#pragma unroll
    for (int oo = 0; oo < 4; oo++) {
        int o = o0 + ty * 4 + oo;
        uint2 pk;
        pk.x = pack_bf16(acc[oo][0] + bs[oo], acc[oo][1] + bs[oo]);
        pk.y = pack_bf16(acc[oo][2] + bs[oo], acc[oo][3] + bs[oo]);
        *(uint2*)(out + ((size_t)b * C_ + o) * N_ + n0 + tx * 4) = pk;
    }
}

// ---------------------------------------------------------------------------
// Flash attention, bf16 m16n8k16 tensor cores, fp32 softmax in registers.
// Per CTA = (batch, 64-query tile). 64-key tiles, 3 barriers/tile.
// GEMM1: warp w -> queries [(w>>1)*16,+16), keys [(w&1)*32,+32).
// GEMM2: warp w -> all 64 queries, channels [w*32,+32).
// ---------------------------------------------------------------------------
// SMEM (bytes):
//  qs  [64][40] bf16   @0      (5120)   [query][channel]
//  ks  [2][64][40] bf16 @5120  (10240)  [key][channel]
//  pb  [64][72] bf16   @15360  (9216)   [query][key] probs
//  vs  [2][256][72] bf16 @24576 (73728) [channel][key]
//  msh/lsh/csh f32[64] @98304/98560/98816
//  pmax f32[2][64]     @99072  (512)
//  psum f32[2][64]     @99584  (512)
#define QS_S 40
#define KS_S 40
#define PB_S 72
#define VS_S 72
#define ATTN_SMEM_BYTES 100096
#define NTILES (N_ / 64)

__global__ __launch_bounds__(256, 2)
void attn_kernel(const __nv_bfloat16* __restrict__ q,
                 const __nv_bfloat16* __restrict__ k,
                 const __nv_bfloat16* __restrict__ v,
                 const float* __restrict__ x,
                 const float* __restrict__ gamma, float* __restrict__ out)
{
    extern __shared__ __align__(16) char smr[];
    __nv_bfloat16* qs  = (__nv_bfloat16*)(smr);
    __nv_bfloat16* ks0 = (__nv_bfloat16*)(smr + 5120);
    __nv_bfloat16* ks1 = (__nv_bfloat16*)(smr + 10240);
    __nv_bfloat16* pb  = (__nv_bfloat16*)(smr + 15360);
    __nv_bfloat16* vs0 = (__nv_bfloat16*)(smr + 24576);
    __nv_bfloat16* vs1 = (__nv_bfloat16*)(smr + 61440);
    float* msh   = (float*)(smr + 98304);
    float* lsh   = (float*)(smr + 98560);
    float* csh   = (float*)(smr + 98816);
    float* pmaxs = (float*)(smr + 99072);   // [2][64]
    float* psums = (float*)(smr + 99584);   // [2][64]

    const int b   = blockIdx.y;
    const int qb0 = blockIdx.x * 64;
    const int t   = threadIdx.x;

    const __nv_bfloat16* qp = q + ((size_t)b * N_ + qb0) * CQ_;
    const __nv_bfloat16* kp = k + (size_t)b * N_ * CQ_;
    const __nv_bfloat16* vp = v + (size_t)b * C_ * N_;

    // ---- preamble: q tile, init, prefetch tile 0 ----
    {   // q: 64 rows x 64B
        int qi = t >> 2, ch = (t & 3) * 8;
        *(uint4*)(qs + qi * QS_S + ch) = *(const uint4*)(qp + qi * CQ_ + ch);
    }
    if (t < 64) { msh[t] = -INFINITY; lsh[t] = 0.f; }
    {   // K tile 0: 64 keys x 64B
        int key = t >> 2, ch = (t & 3) * 8;
        cp16(ks0 + key * KS_S + ch, kp + key * CQ_ + ch);
#pragma unroll
        for (int r = 0; r < 8; r++) {
            int idx = t + r * 256;
            int c  = idx >> 3, k8 = (idx & 7) * 8;
            cp16(vs0 + c * VS_S + k8, vp + (size_t)c * N_ + k8);
        }
        cp_commit();
    }
    __syncthreads();   // qs visible

    // warp/fragment coordinates
    const int wid  = t >> 5;
    const int lane = t & 31;
    const int gid  = lane >> 2;        // 0..7
    const int tig  = lane & 3;         // 0..3
    const int m0   = (wid >> 1) * 16;  // GEMM1 query-tile base
    const int n1   = (wid & 1) * 32;   // GEMM1 key base (4 n-tiles)
    const int wh   = wid & 1;          // warp half (pmax/psum slot)
    const int ch0  = wid * 32;         // GEMM2 channel base
    const int row0 = m0 + gid;
    const int row1 = m0 + gid + 8;

    // preload Q A-fragments (tile-invariant): qa[kt][4]
    uint32_t qa[2][4];
#pragma unroll
    for (int kt = 0; kt < 2; kt++) {
        const __nv_bfloat16* qr0 = qs + row0 * QS_S + kt * 16;
        const __nv_bfloat16* qr1 = qs + row1 * QS_S + kt * 16;
        qa[kt][0] = *(const uint32_t*)(qr0 + 2 * tig);
        qa[kt][1] = *(const uint32_t*)(qr1 + 2 * tig);
        qa[kt][2] = *(const uint32_t*)(qr0 + 2 * tig + 8);
        qa[kt][3] = *(const uint32_t*)(qr1 + 2 * tig + 8);
    }

    // O accumulators: [m-tile][n-tile][4]
    float oa[4][4][4];
#pragma unroll
    for (int mt = 0; mt < 4; mt++)
#pragma unroll
        for (int nt = 0; nt < 4; nt++)
#pragma unroll
            for (int r = 0; r < 4; r++) oa[mt][nt][r] = 0.f;

    for (int it = 0; it < NTILES; it++) {
        const __nv_bfloat16* ks = (it & 1) ? ks1 : ks0;
        const __nv_bfloat16* vs = (it & 1) ? vs1 : vs0;

        cp_wait<0>();
        __syncthreads();   // A: tiles ready, prev GEMM2 done (pb free)

        // prefetch tile it+1 (target buffer idle since barrier A)
        if (it + 1 < NTILES) {
            __nv_bfloat16* ksn = (it & 1) ? ks0 : ks1;
            __nv_bfloat16* vsn = (it & 1) ? vs0 : vs1;
            int j0n = (it + 1) * 64;
            int key = t >> 2, ch = (t & 3) * 8;
            cp16(ksn + key * KS_S + ch, kp + (size_t)(j0n + key) * CQ_ + ch);
#pragma unroll
            for (int r = 0; r < 8; r++) {
                int idx = t + r * 256;
                int c  = idx >> 3, k8 = (idx & 7) * 8;
                cp16(vsn + c * VS_S + k8, vp + (size_t)c * N_ + j0n + k8);
            }
            cp_commit();
        }

        // ---- GEMM1: S[16q x 32k] per warp, in registers ----
        float s[4][4];
#pragma unroll
        for (int nt = 0; nt < 4; nt++)
#pragma unroll
            for (int r = 0; r < 4; r++) s[nt][r] = 0.f;
#pragma unroll
        for (int kt = 0; kt < 2; kt++) {
#pragma unroll
            for (int nt = 0; nt < 4; nt++) {
                const __nv_bfloat16* kr = ks + (n1 + nt * 8 + gid) * KS_S + kt * 16;
                uint32_t b0 = *(const uint32_t*)(kr + 2 * tig);
                uint32_t b1 = *(const uint32_t*)(kr + 2 * tig + 8);
                mma16(s[nt], qa[kt], b0, b1);
            }
        }

        // warp-level row max over this warp's 32 keys
        float mx0 = s[0][0], mx1 = s[0][2];
#pragma unroll
        for (int nt = 0; nt < 4; nt++) {
            mx0 = fmaxf(mx0, fmaxf(s[nt][0], s[nt][1]));
            mx1 = fmaxf(mx1, fmaxf(s[nt][2], s[nt][3]));
        }
        mx0 = fmaxf(mx0, __shfl_xor_sync(0xffffffffu, mx0, 1));
        mx0 = fmaxf(mx0, __shfl_xor_sync(0xffffffffu, mx0, 2));
        mx1 = fmaxf(mx1, __shfl_xor_sync(0xffffffffu, mx1, 1));
        mx1 = fmaxf(mx1, __shfl_xor_sync(0xffffffffu, mx1, 2));
        if (tig == 0) {
            pmaxs[wh * 64 + row0] = mx0;
            pmaxs[wh * 64 + row1] = mx1;
        }
        // read old maxes BEFORE barrier B (writers update after B)
        float mo0 = msh[row0];
        float mo1 = msh[row1];
        __syncthreads();   // B: pmax ready

        // ---- softmax on registers ----
        {
            float fx0 = fmaxf(fmaxf(pmaxs[row0], pmaxs[64 + row0]), mo0);
            float fx1 = fmaxf(fmaxf(pmaxs[row1], pmaxs[64 + row1]), mo1);
            float sum0 = 0.f, sum1 = 0.f;
#pragma unroll
            for (int nt = 0; nt < 4; nt++) {
                float p0 = __expf(s[nt][0] - fx0);
                float p1 = __expf(s[nt][1] - fx0);
                float p2 = __expf(s[nt][2] - fx1);
                float p3 = __expf(s[nt][3] - fx1);
                int jc = n1 + nt * 8 + 2 * tig;
                *(uint32_t*)(pb + row0 * PB_S + jc) = pack_bf16(p0, p1);
                *(uint32_t*)(pb + row1 * PB_S + jc) = pack_bf16(p2, p3);
                sum0 += p0 + p1;
                sum1 += p2 + p3;
            }
            sum0 += __shfl_xor_sync(0xffffffffu, sum0, 1);
            sum0 += __shfl_xor_sync(0xffffffffu, sum0, 2);
            sum1 += __shfl_xor_sync(0xffffffffu, sum1, 1);
            sum1 += __shfl_xor_sync(0xffffffffu, sum1, 2);
            if (tig == 0) {
                psums[wh * 64 + row0] = sum0;
                psums[wh * 64 + row1] = sum1;
                if (wh == 0) {
                    msh[row0] = fx0;  csh[row0] = __expf(mo0 - fx0);
                    msh[row1] = fx1;  csh[row1] = __expf(mo1 - fx1);
                }
            }
        }
        __syncthreads();   // C: pb, psum, csh ready

        // ---- l update + O rescale + GEMM2 ----
        if (t < 64) lsh[t] = lsh[t] * csh[t] + psums[t] + psums[64 + t];
#pragma unroll
        for (int mt = 0; mt < 4; mt++) {
            float cr0 = csh[mt * 16 + gid];
            float cr1 = csh[mt * 16 + gid + 8];
#pragma unroll
            for (int nt = 0; nt < 4; nt++) {
                oa[mt][nt][0] *= cr0; oa[mt][nt][1] *= cr0;
                oa[mt][nt][2] *= cr1; oa[mt][nt][3] *= cr1;
            }
        }
#pragma unroll
        for (int kt = 0; kt < 4; kt++) {
            uint32_t vb[4][2];
#pragma unroll
            for (int nt = 0; nt < 4; nt++) {
                const __nv_bfloat16* vr = vs + (ch0 + nt * 8 + gid) * VS_S + kt * 16;
                vb[nt][0] = *(const uint32_t*)(vr + 2 * tig);
                vb[nt][1] = *(const uint32_t*)(vr + 2 * tig + 8);
            }
#pragma unroll
            for (int mt = 0; mt < 4; mt++) {
                const __nv_bfloat16* pr0 = pb + (mt * 16 + gid) * PB_S + kt * 16;
                const __nv_bfloat16* pr1 = pb + (mt * 16 + gid + 8) * PB_S + kt * 16;
                uint32_t pA[4];
                pA[0] = *(const uint32_t*)(pr0 + 2 * tig);
                pA[1] = *(const uint32_t*)(pr1 + 2 * tig);
                pA[2] = *(const uint32_t*)(pr0 + 2 * tig + 8);
                pA[3] = *(const uint32_t*)(pr1 + 2 * tig + 8);
#pragma unroll
                for (int nt = 0; nt < 4; nt++)
                    mma16(oa[mt][nt], pA, vb[nt][0], vb[nt][1]);
            }
        }
        // no trailing barrier: next iter's barrier A protects pb/vs
    }
    __syncthreads();   // lsh stable

    // ---- epilogue: out = gamma * O / l + x ----
    float g = gamma[0];
#pragma unroll
    for (int mt = 0; mt < 4; mt++) {
        float il0 = 1.f / lsh[mt * 16 + gid];
        float il1 = 1.f / lsh[mt * 16 + gid + 8];
        int r0 = qb0 + mt * 16 + gid;
        int r1 = r0 + 8;
#pragma unroll
        for (int nt = 0; nt < 4; nt++) {
            int c = ch0 + nt * 8 + 2 * tig;
            const float* x0 = x + ((size_t)b * C_ + c) * N_;
            float*       o0 = out + ((size_t)b * C_ + c) * N_;
            o0[r0]      = g * oa[mt][nt][0] * il0 + x0[r0];
            o0[N_ + r0] = g * oa[mt][nt][1] * il0 + x0[N_ + r0];
            o0[r1]      = g * oa[mt][nt][2] * il1 + x0[r1];
            o0[N_ + r1] = g * oa[mt][nt][3] * il1 + x0[N_ + r1];
        }
    }
}

// ---------------------------------------------------------------------------
// Launch
// ---------------------------------------------------------------------------
extern "C" void kernel_launch(void* const* d_in, const int* in_sizes, int n_in,
                              void* d_out, int out_size)
{
    const float* x     = (const float*)d_in[0];
    const float* mask  = (const float*)d_in[1];
    const float* Wq    = (const float*)d_in[2];
    const float* bq    = (const float*)d_in[3];
    const float* Wk    = (const float*)d_in[4];
    const float* bk    = (const float*)d_in[5];
    const float* Wv    = (const float*)d_in[6];
    const float* bv    = (const float*)d_in[7];
    const float* gamma = (const float*)d_in[8];
    float* out = (float*)d_out;

    __nv_bfloat16 *gq, *gk, *gv;
    cudaGetSymbolAddress((void**)&gq, g_q);
    cudaGetSymbolAddress((void**)&gk, g_k);
    cudaGetSymbolAddress((void**)&gv, g_v);

    cudaFuncSetAttribute(attn_kernel,
                         cudaFuncAttributeMaxDynamicSharedMemorySize,
                         ATTN_SMEM_BYTES);

    qk_proj_kernel<<<dim3(N_ / 128, 2, B_), 256>>>(x, Wq, bq, Wk, bk, mask, gq, gk);
    v_proj_kernel <<<dim3(N_ / 128, C_ / 32, B_), 256>>>(x, Wv, bv, gv);
    attn_kernel<<<dim3(N_ / 64, B_), 256, ATTN_SMEM_BYTES>>>(gq, gk, gv, x, gamma, out);
}

// round 12
// speedup vs baseline: 5.1493x; 1.2534x over previous
#include <cuda_runtime.h>
#include <cuda_bf16.h>
#include <cstdint>

// Problem constants (fixed by reference: B=4, C=256, CQ=32, H=W=64)
#define B_   4
#define C_   256
#define CQ_  32
#define N_   4096

typedef unsigned long long u64;

// Scratch (allocation-free rule: __device__ globals)
__device__ __nv_bfloat16 g_xt[B_ * N_ * C_];   // [B][N][C]   x transposed, bf16
__device__ __nv_bfloat16 g_q[B_ * N_ * CQ_];   // [B][N][CQ]  (masked, channel-contig)
__device__ __nv_bfloat16 g_k[B_ * N_ * CQ_];   // [B][N][CQ]  (masked, channel-contig)
__device__ __nv_bfloat16 g_v[B_ * C_ * N_];    // [B][C][N]   (key-contig)

// ---------------------------------------------------------------------------
// Helpers
// ---------------------------------------------------------------------------
__device__ __forceinline__ uint32_t pack_bf16(float lo, float hi) {
    __nv_bfloat162 h = __floats2bfloat162_rn(lo, hi);   // .x = lo (low 16 bits)
    return *(uint32_t*)&h;
}

// mma m16n8k16 bf16: D = A*B + D (fp32 accumulate)
__device__ __forceinline__ void mma16(float* d, const uint32_t* a,
                                      uint32_t b0, uint32_t b1) {
    asm("mma.sync.aligned.m16n8k16.row.col.f32.bf16.bf16.f32 "
        "{%0,%1,%2,%3},{%4,%5,%6,%7},{%8,%9},{%0,%1,%2,%3};"
        : "+f"(d[0]), "+f"(d[1]), "+f"(d[2]), "+f"(d[3])
        : "r"(a[0]), "r"(a[1]), "r"(a[2]), "r"(a[3]), "r"(b0), "r"(b1));
}

// cp.async helpers (.cg = L2-only streaming)
__device__ __forceinline__ void cp16(void* smem, const void* g) {
    unsigned s = (unsigned)__cvta_generic_to_shared(smem);
    asm volatile("cp.async.cg.shared.global [%0], [%1], 16;" :: "r"(s), "l"(g));
}
__device__ __forceinline__ void cp_commit() {
    asm volatile("cp.async.commit_group;");
}
template <int N>
__device__ __forceinline__ void cp_wait() {
    asm volatile("cp.async.wait_group %0;" :: "n"(N));
}

// ---------------------------------------------------------------------------
// Transpose + convert: x [b][c][n] f32 -> xt [b][n][c] bf16.
// Tile 32c x 128n. Conflict-free via [128][33] staging.
// ---------------------------------------------------------------------------
__global__ __launch_bounds__(256)
void transpose_cvt_kernel(const float* __restrict__ X,
                          __nv_bfloat16* __restrict__ xt)
{
    __shared__ float sm_t[128][33];
    const int b  = blockIdx.z;
    const int c0 = blockIdx.y * 32;
    const int n0 = blockIdx.x * 128;
    const int t  = threadIdx.x;

#pragma unroll
    for (int r = 0; r < 16; r++) {
        int idx = t + r * 256;
        int j = idx & 127, c = idx >> 7;
        sm_t[j][c] = X[((size_t)b * C_ + c0 + c) * N_ + n0 + j];
    }
    __syncthreads();

    const int j  = t >> 1;
    const int cc = (t & 1) * 16;
    uint32_t pk[8];
#pragma unroll
    for (int i = 0; i < 8; i++)
        pk[i] = pack_bf16(sm_t[j][cc + 2 * i], sm_t[j][cc + 2 * i + 1]);
    __nv_bfloat16* dst = xt + ((size_t)b * N_ + n0 + j) * C_ + c0 + cc;
    *(uint4*)dst       = *(uint4*)&pk[0];
    *(uint4*)(dst + 8) = *(uint4*)&pk[4];
}

// ---------------------------------------------------------------------------
// QK projection on tensor cores: out[n][o] = xt[n][:] . W[o][:] (+bias)*mask.
// A = xt rows (row-major), B = W rows (col-major over K=c).
// CTA: 128 n x 32 o, K=256. blockIdx.y selects q/k.
// SMEM: xs [128][280] bf16 (71680 B) + wsm [32][280] bf16 (17920 B) = 89600 B.
// Stride 280 bf16 = 140 words ≡ 12 (mod 32) -> bank 12*gid+tig: conflict-free.
// ---------------------------------------------------------------------------
#define XP_S 280
#define QKP_SMEM (128 * XP_S * 2 + 32 * XP_S * 2)

__global__ __launch_bounds__(256)
void qk_proj_kernel(const __nv_bfloat16* __restrict__ xt,
                    const float* __restrict__ Wq, const float* __restrict__ bq,
                    const float* __restrict__ Wk, const float* __restrict__ bk,
                    const float* __restrict__ mask,
                    __nv_bfloat16* __restrict__ outq,
                    __nv_bfloat16* __restrict__ outk)
{
    extern __shared__ __align__(16) char smr[];
    __nv_bfloat16* xs  = (__nv_bfloat16*)smr;                    // [128][280]
    __nv_bfloat16* wsm = (__nv_bfloat16*)(smr + 128 * XP_S * 2); // [32][280]

    const int b  = blockIdx.z;
    const int n0 = blockIdx.x * 128;
    const int t  = threadIdx.x;
    const bool isK = blockIdx.y != 0;
    const float* W    = isK ? Wk : Wq;
    const float* bias = isK ? bk : bq;
    __nv_bfloat16* out = isK ? outk : outq;

    // xt tile via cp.async: 128 rows x 256 bf16 (32 cp16/row)
    const __nv_bfloat16* xp = xt + ((size_t)b * N_ + n0) * C_;
#pragma unroll
    for (int r = 0; r < 16; r++) {
        int idx = t + r * 256;
        int row = idx >> 5, ch = (idx & 31) * 8;
        cp16(xs + row * XP_S + ch, xp + (size_t)row * C_ + ch);
    }
    cp_commit();

    // W (32x256 f32) -> bf16 smem
#pragma unroll
    for (int r = 0; r < 8; r++) {
        int idx = t + r * 256;
        int o = idx >> 6, c4 = (idx & 63) * 4;
        float4 w = *(const float4*)(W + (size_t)o * C_ + c4);
        uint2 pk;
        pk.x = pack_bf16(w.x, w.y);
        pk.y = pack_bf16(w.z, w.w);
        *(uint2*)(wsm + o * XP_S + c4) = pk;
    }
    cp_wait<0>();
    __syncthreads();

    const int wid = t >> 5, lane = t & 31;
    const int gid = lane >> 2, tig = lane & 3;
    const int m0  = wid * 16;          // n-row tile

    float s[4][4];
#pragma unroll
    for (int nt = 0; nt < 4; nt++)
#pragma unroll
        for (int r = 0; r < 4; r++) s[nt][r] = 0.f;

#pragma unroll
    for (int kt = 0; kt < 16; kt++) {
        const __nv_bfloat16* ar0 = xs + (m0 + gid)     * XP_S + kt * 16;
        const __nv_bfloat16* ar1 = xs + (m0 + gid + 8) * XP_S + kt * 16;
        uint32_t a[4];
        a[0] = *(const uint32_t*)(ar0 + 2 * tig);
        a[1] = *(const uint32_t*)(ar1 + 2 * tig);
        a[2] = *(const uint32_t*)(ar0 + 2 * tig + 8);
        a[3] = *(const uint32_t*)(ar1 + 2 * tig + 8);
#pragma unroll
        for (int nt = 0; nt < 4; nt++) {
            const __nv_bfloat16* br = wsm + (nt * 8 + gid) * XP_S + kt * 16;
            uint32_t b0 = *(const uint32_t*)(br + 2 * tig);
            uint32_t b1 = *(const uint32_t*)(br + 2 * tig + 8);
            mma16(s[nt], a, b0, b1);
        }
    }

    // epilogue: (acc + bias[o]) * mask[n], pack pairs, store [n][CQ]
    int nr0 = n0 + m0 + gid;
    int nr1 = nr0 + 8;
    float mk0 = mask[(size_t)b * N_ + nr0];
    float mk1 = mask[(size_t)b * N_ + nr1];
#pragma unroll
    for (int nt = 0; nt < 4; nt++) {
        int o = nt * 8 + 2 * tig;
        float b0v = bias[o], b1v = bias[o + 1];
        *(uint32_t*)(out + ((size_t)b * N_ + nr0) * CQ_ + o) =
            pack_bf16((s[nt][0] + b0v) * mk0, (s[nt][1] + b1v) * mk0);
        *(uint32_t*)(out + ((size_t)b * N_ + nr1) * CQ_ + o) =
            pack_bf16((s[nt][2] + b0v) * mk1, (s[nt][3] + b1v) * mk1);
    }
}

// ---------------------------------------------------------------------------
// V projection on tensor cores: out[o][n] = W[o][:] . xt[n][:] (+bias).
// A = W rows (row-major), B = xt rows (col-major over K=c).
// CTA: 64 o x 128 n, K=256.
// SMEM: xs [128][280] (71680) + wsm [64][280] (35840) = 107520 B.
// ---------------------------------------------------------------------------
#define VP_SMEM (128 * XP_S * 2 + 64 * XP_S * 2)

__global__ __launch_bounds__(256)
void v_proj_kernel(const __nv_bfloat16* __restrict__ xt,
                   const float* __restrict__ W, const float* __restrict__ bias,
                   __nv_bfloat16* __restrict__ out)
{
    extern __shared__ __align__(16) char smr[];
    __nv_bfloat16* xs  = (__nv_bfloat16*)smr;                    // [128][280]
    __nv_bfloat16* wsm = (__nv_bfloat16*)(smr + 128 * XP_S * 2); // [64][280]

    const int b  = blockIdx.z;
    const int o0 = blockIdx.y * 64;
    const int n0 = blockIdx.x * 128;
    const int t  = threadIdx.x;

    const __nv_bfloat16* xp = xt + ((size_t)b * N_ + n0) * C_;
#pragma unroll
    for (int r = 0; r < 16; r++) {
        int idx = t + r * 256;
        int row = idx >> 5, ch = (idx & 31) * 8;
        cp16(xs + row * XP_S + ch, xp + (size_t)row * C_ + ch);
    }
    cp_commit();

    // W (64x256 f32) -> bf16 smem
#pragma unroll
    for (int r = 0; r < 16; r++) {
        int idx = t + r * 256;
        int o = idx >> 6, c4 = (idx & 63) * 4;
        float4 w = *(const float4*)(W + (size_t)(o0 + o) * C_ + c4);
        uint2 pk;
        pk.x = pack_bf16(w.x, w.y);
        pk.y = pack_bf16(w.z, w.w);
        *(uint2*)(wsm + o * XP_S + c4) = pk;
    }
    cp_wait<0>();
    __syncthreads();

    const int wid = t >> 5, lane = t & 31;
    const int gid = lane >> 2, tig = lane & 3;
    const int m0  = (wid >> 1) * 16;       // o-row tile
    const int nh  = (wid & 1) * 64;        // n half (8 n-tiles)

    float s[8][4];
#pragma unroll
    for (int nt = 0; nt < 8; nt++)
#pragma unroll
        for (int r = 0; r < 4; r++) s[nt][r] = 0.f;

#pragma unroll
    for (int kt = 0; kt < 16; kt++) {
        const __nv_bfloat16* ar0 = wsm + (m0 + gid)     * XP_S + kt * 16;
        const __nv_bfloat16* ar1 = wsm + (m0 + gid + 8) * XP_S + kt * 16;
        uint32_t a[4];
        a[0] = *(const uint32_t*)(ar0 + 2 * tig);
        a[1] = *(const uint32_t*)(ar1 + 2 * tig);
        a[2] = *(const uint32_t*)(ar0 + 2 * tig + 8);
        a[3] = *(const uint32_t*)(ar1 + 2 * tig + 8);
#pragma unroll
        for (int nt = 0; nt < 8; nt++) {
            const __nv_bfloat16* br = xs + (nh + nt * 8 + gid) * XP_S + kt * 16;
            uint32_t b0 = *(const uint32_t*)(br + 2 * tig);
            uint32_t b1 = *(const uint32_t*)(br + 2 * tig + 8);
            mma16(s[nt], a, b0, b1);
        }
    }

    // epilogue: acc + bias[o], pack n pairs, store [o][n]
    int or0 = o0 + m0 + gid;
    int or1 = or0 + 8;
    float b0v = bias[or0];
    float b1v = bias[or1];
#pragma unroll
    for (int nt = 0; nt < 8; nt++) {
        int n = n0 + nh + nt * 8 + 2 * tig;
        *(uint32_t*)(out + ((size_t)b * C_ + or0) * N_ + n) =
            pack_bf16(s[nt][0] + b0v, s[nt][1] + b0v);
        *(uint32_t*)(out + ((size_t)b * C_ + or1) * N_ + n) =
            pack_bf16(s[nt][2] + b1v, s[nt][3] + b1v);
    }
}

// ---------------------------------------------------------------------------
// Flash attention, bf16 m16n8k16 tensor cores, fp32 softmax in registers.
// (unchanged from the 262us passing version)
// ---------------------------------------------------------------------------
#define QS_S 40
#define KS_S 40
#define PB_S 72
#define VS_S 72
#define ATTN_SMEM_BYTES 100096
#define NTILES (N_ / 64)

__global__ __launch_bounds__(256, 2)
void attn_kernel(const __nv_bfloat16* __restrict__ q,
                 const __nv_bfloat16* __restrict__ k,
                 const __nv_bfloat16* __restrict__ v,
                 const float* __restrict__ x,
                 const float* __restrict__ gamma, float* __restrict__ out)
{
    extern __shared__ __align__(16) char smr[];
    __nv_bfloat16* qs  = (__nv_bfloat16*)(smr);
    __nv_bfloat16* ks0 = (__nv_bfloat16*)(smr + 5120);
    __nv_bfloat16* ks1 = (__nv_bfloat16*)(smr + 10240);
    __nv_bfloat16* pb  = (__nv_bfloat16*)(smr + 15360);
    __nv_bfloat16* vs0 = (__nv_bfloat16*)(smr + 24576);
    __nv_bfloat16* vs1 = (__nv_bfloat16*)(smr + 61440);
    float* msh   = (float*)(smr + 98304);
    float* lsh   = (float*)(smr + 98560);
    float* csh   = (float*)(smr + 98816);
    float* pmaxs = (float*)(smr + 99072);
    float* psums = (float*)(smr + 99584);

    const int b   = blockIdx.y;
    const int qb0 = blockIdx.x * 64;
    const int t   = threadIdx.x;

    const __nv_bfloat16* qp = q + ((size_t)b * N_ + qb0) * CQ_;
    const __nv_bfloat16* kp = k + (size_t)b * N_ * CQ_;
    const __nv_bfloat16* vp = v + (size_t)b * C_ * N_;

    {   // q: 64 rows x 64B
        int qi = t >> 2, ch = (t & 3) * 8;
        *(uint4*)(qs + qi * QS_S + ch) = *(const uint4*)(qp + qi * CQ_ + ch);
    }
    if (t < 64) { msh[t] = -INFINITY; lsh[t] = 0.f; }
    {   // K tile 0
        int key = t >> 2, ch = (t & 3) * 8;
        cp16(ks0 + key * KS_S + ch, kp + key * CQ_ + ch);
#pragma unroll
        for (int r = 0; r < 8; r++) {
            int idx = t + r * 256;
            int c  = idx >> 3, k8 = (idx & 7) * 8;
            cp16(vs0 + c * VS_S + k8, vp + (size_t)c * N_ + k8);
        }
        cp_commit();
    }
    __syncthreads();

    const int wid  = t >> 5;
    const int lane = t & 31;
    const int gid  = lane >> 2;
    const int tig  = lane & 3;
    const int m0   = (wid >> 1) * 16;
    const int n1   = (wid & 1) * 32;
    const int wh   = wid & 1;
    const int ch0  = wid * 32;
    const int row0 = m0 + gid;
    const int row1 = m0 + gid + 8;

    uint32_t qa[2][4];
#pragma unroll
    for (int kt = 0; kt < 2; kt++) {
        const __nv_bfloat16* qr0 = qs + row0 * QS_S + kt * 16;
        const __nv_bfloat16* qr1 = qs + row1 * QS_S + kt * 16;
        qa[kt][0] = *(const uint32_t*)(qr0 + 2 * tig);
        qa[kt][1] = *(const uint32_t*)(qr1 + 2 * tig);
        qa[kt][2] = *(const uint32_t*)(qr0 + 2 * tig + 8);
        qa[kt][3] = *(const uint32_t*)(qr1 + 2 * tig + 8);
    }

    float oa[4][4][4];
#pragma unroll
    for (int mt = 0; mt < 4; mt++)
#pragma unroll
        for (int nt = 0; nt < 4; nt++)
#pragma unroll
            for (int r = 0; r < 4; r++) oa[mt][nt][r] = 0.f;

    for (int it = 0; it < NTILES; it++) {
        const __nv_bfloat16* ks = (it & 1) ? ks1 : ks0;
        const __nv_bfloat16* vs = (it & 1) ? vs1 : vs0;

        cp_wait<0>();
        __syncthreads();

        if (it + 1 < NTILES) {
            __nv_bfloat16* ksn = (it & 1) ? ks0 : ks1;
            __nv_bfloat16* vsn = (it & 1) ? vs0 : vs1;
            int j0n = (it + 1) * 64;
            int key = t >> 2, ch = (t & 3) * 8;
            cp16(ksn + key * KS_S + ch, kp + (size_t)(j0n + key) * CQ_ + ch);
#pragma unroll
            for (int r = 0; r < 8; r++) {
                int idx = t + r * 256;
                int c  = idx >> 3, k8 = (idx & 7) * 8;
                cp16(vsn + c * VS_S + k8, vp + (size_t)c * N_ + j0n + k8);
            }
            cp_commit();
        }

        float s[4][4];
#pragma unroll
        for (int nt = 0; nt < 4; nt++)
#pragma unroll
            for (int r = 0; r < 4; r++) s[nt][r] = 0.f;
#pragma unroll
        for (int kt = 0; kt < 2; kt++) {
#pragma unroll
            for (int nt = 0; nt < 4; nt++) {
                const __nv_bfloat16* kr = ks + (n1 + nt * 8 + gid) * KS_S + kt * 16;
                uint32_t b0 = *(const uint32_t*)(kr + 2 * tig);
                uint32_t b1 = *(const uint32_t*)(kr + 2 * tig + 8);
                mma16(s[nt], qa[kt], b0, b1);
            }
        }

        float mx0 = s[0][0], mx1 = s[0][2];
#pragma unroll
        for (int nt = 0; nt < 4; nt++) {
            mx0 = fmaxf(mx0, fmaxf(s[nt][0], s[nt][1]));
            mx1 = fmaxf(mx1, fmaxf(s[nt][2], s[nt][3]));
        }
        mx0 = fmaxf(mx0, __shfl_xor_sync(0xffffffffu, mx0, 1));
        mx0 = fmaxf(mx0, __shfl_xor_sync(0xffffffffu, mx0, 2));
        mx1 = fmaxf(mx1, __shfl_xor_sync(0xffffffffu, mx1, 1));
        mx1 = fmaxf(mx1, __shfl_xor_sync(0xffffffffu, mx1, 2));
        if (tig == 0) {
            pmaxs[wh * 64 + row0] = mx0;
            pmaxs[wh * 64 + row1] = mx1;
        }
        float mo0 = msh[row0];
        float mo1 = msh[row1];
        __syncthreads();

        {
            float fx0 = fmaxf(fmaxf(pmaxs[row0], pmaxs[64 + row0]), mo0);
            float fx1 = fmaxf(fmaxf(pmaxs[row1], pmaxs[64 + row1]), mo1);
            float sum0 = 0.f, sum1 = 0.f;
#pragma unroll
            for (int nt = 0; nt < 4; nt++) {
                float p0 = __expf(s[nt][0] - fx0);
                float p1 = __expf(s[nt][1] - fx0);
                float p2 = __expf(s[nt][2] - fx1);
                float p3 = __expf(s[nt][3] - fx1);
                int jc = n1 + nt * 8 + 2 * tig;
                *(uint32_t*)(pb + row0 * PB_S + jc) = pack_bf16(p0, p1);
                *(uint32_t*)(pb + row1 * PB_S + jc) = pack_bf16(p2, p3);
                sum0 += p0 + p1;
                sum1 += p2 + p3;
            }
            sum0 += __shfl_xor_sync(0xffffffffu, sum0, 1);
            sum0 += __shfl_xor_sync(0xffffffffu, sum0, 2);
            sum1 += __shfl_xor_sync(0xffffffffu, sum1, 1);
            sum1 += __shfl_xor_sync(0xffffffffu, sum1, 2);
            if (tig == 0) {
                psums[wh * 64 + row0] = sum0;
                psums[wh * 64 + row1] = sum1;
                if (wh == 0) {
                    msh[row0] = fx0;  csh[row0] = __expf(mo0 - fx0);
                    msh[row1] = fx1;  csh[row1] = __expf(mo1 - fx1);
                }
            }
        }
        __syncthreads();

        if (t < 64) lsh[t] = lsh[t] * csh[t] + psums[t] + psums[64 + t];
#pragma unroll
        for (int mt = 0; mt < 4; mt++) {
            float cr0 = csh[mt * 16 + gid];
            float cr1 = csh[mt * 16 + gid + 8];
#pragma unroll
            for (int nt = 0; nt < 4; nt++) {
                oa[mt][nt][0] *= cr0; oa[mt][nt][1] *= cr0;
                oa[mt][nt][2] *= cr1; oa[mt][nt][3] *= cr1;
            }
        }
#pragma unroll
        for (int kt = 0; kt < 4; kt++) {
            uint32_t vb[4][2];
#pragma unroll
            for (int nt = 0; nt < 4; nt++) {
                const __nv_bfloat16* vr = vs + (ch0 + nt * 8 + gid) * VS_S + kt * 16;
                vb[nt][0] = *(const uint32_t*)(vr + 2 * tig);
                vb[nt][1] = *(const uint32_t*)(vr + 2 * tig + 8);
            }
#pragma unroll
            for (int mt = 0; mt < 4; mt++) {
                const __nv_bfloat16* pr0 = pb + (mt * 16 + gid) * PB_S + kt * 16;
                const __nv_bfloat16* pr1 = pb + (mt * 16 + gid + 8) * PB_S + kt * 16;
                uint32_t pA[4];
                pA[0] = *(const uint32_t*)(pr0 + 2 * tig);
                pA[1] = *(const uint32_t*)(pr1 + 2 * tig);
                pA[2] = *(const uint32_t*)(pr0 + 2 * tig + 8);
                pA[3] = *(const uint32_t*)(pr1 + 2 * tig + 8);
#pragma unroll
                for (int nt = 0; nt < 4; nt++)
                    mma16(oa[mt][nt], pA, vb[nt][0], vb[nt][1]);
            }
        }
    }
    __syncthreads();

    float g = gamma[0];
#pragma unroll
    for (int mt = 0; mt < 4; mt++) {
        float il0 = 1.f / lsh[mt * 16 + gid];
        float il1 = 1.f / lsh[mt * 16 + gid + 8];
        int r0 = qb0 + mt * 16 + gid;
        int r1 = r0 + 8;
#pragma unroll
        for (int nt = 0; nt < 4; nt++) {
            int c = ch0 + nt * 8 + 2 * tig;
            const float* x0 = x + ((size_t)b * C_ + c) * N_;
            float*       o0 = out + ((size_t)b * C_ + c) * N_;
            o0[r0]      = g * oa[mt][nt][0] * il0 + x0[r0];
            o0[N_ + r0] = g * oa[mt][nt][1] * il0 + x0[N_ + r0];
            o0[r1]      = g * oa[mt][nt][2] * il1 + x0[r1];
            o0[N_ + r1] = g * oa[mt][nt][3] * il1 + x0[N_ + r1];
        }
    }
}

// ---------------------------------------------------------------------------
// Launch
// ---------------------------------------------------------------------------
extern "C" void kernel_launch(void* const* d_in, const int* in_sizes, int n_in,
                              void* d_out, int out_size)
{
    const float* x     = (const float*)d_in[0];
    const float* mask  = (const float*)d_in[1];
    const float* Wq    = (const float*)d_in[2];
    const float* bq    = (const float*)d_in[3];
    const float* Wk    = (const float*)d_in[4];
    const float* bk    = (const float*)d_in[5];
    const float* Wv    = (const float*)d_in[6];
    const float* bv    = (const float*)d_in[7];
    const float* gamma = (const float*)d_in[8];
    float* out = (float*)d_out;

    __nv_bfloat16 *gxt, *gq, *gk, *gv;
    cudaGetSymbolAddress((void**)&gxt, g_xt);
    cudaGetSymbolAddress((void**)&gq, g_q);
    cudaGetSymbolAddress((void**)&gk, g_k);
    cudaGetSymbolAddress((void**)&gv, g_v);

    cudaFuncSetAttribute(qk_proj_kernel,
                         cudaFuncAttributeMaxDynamicSharedMemorySize, QKP_SMEM);
    cudaFuncSetAttribute(v_proj_kernel,
                         cudaFuncAttributeMaxDynamicSharedMemorySize, VP_SMEM);
    cudaFuncSetAttribute(attn_kernel,
                         cudaFuncAttributeMaxDynamicSharedMemorySize,
                         ATTN_SMEM_BYTES);

    transpose_cvt_kernel<<<dim3(N_ / 128, C_ / 32, B_), 256>>>(x, gxt);
    qk_proj_kernel<<<dim3(N_ / 128, 2, B_), 256, QKP_SMEM>>>(gxt, Wq, bq, Wk, bk, mask, gq, gk);
    v_proj_kernel <<<dim3(N_ / 128, C_ / 64, B_), 256, VP_SMEM>>>(gxt, Wv, bv, gv);
    attn_kernel<<<dim3(N_ / 64, B_), 256, ATTN_SMEM_BYTES>>>(gq, gk, gv, x, gamma, out);
}